// round 6
// baseline (speedup 1.0000x reference)
#include <cuda_runtime.h>
#include <cstdint>

// ---------------------------------------------------------------------------
// out[n,o,h,w] = sum_{c,kw} x[n,c,(h-1)%56, w+kw-1] * wgt[o,c,kw]
// N=128, C=128, H=W=56, O=32, KW=3 (pad W by 1 each side).
// Per (n,h): GEMM C[32,56] = W[32,384] * X[384,56], done as 3 accumulating
// K=128 GEMMs (one per kw) over shifted views of the smem-staged x row,
// using mma.sync.m16n8k8 tf32.
// ---------------------------------------------------------------------------

namespace {

constexpr int ROWS_PER_BLK = 4;      // (n,h) rows per block
constexpr int XSTRIDE      = 72;     // smem floats per c-row; 72 % 32 == 8 -> conflict-free B loads
constexpr int XS_PER_ROW   = 128 * XSTRIDE;            // 9216 floats
constexpr int XS_FLOATS    = ROWS_PER_BLK * XS_PER_ROW; // 36864 floats
constexpr int AFR_U32      = 3 * 2 * 16 * 32 * 4;       // kw * mtile * kstep * lane * 4 regs = 12288
constexpr int SMEM_BYTES   = (XS_FLOATS + AFR_U32) * 4; // 196608 B

__device__ __forceinline__ unsigned f2tf32(float f) {
    unsigned u;
    asm("cvt.rna.tf32.f32 %0, %1;" : "=r"(u) : "f"(f));
    return u;
}

__device__ __forceinline__ void mma_tf32(float d[4], const uint4& a,
                                         unsigned b0, unsigned b1) {
    asm volatile(
        "mma.sync.aligned.m16n8k8.row.col.f32.tf32.tf32.f32 "
        "{%0,%1,%2,%3}, {%4,%5,%6,%7}, {%8,%9}, {%0,%1,%2,%3};"
        : "+f"(d[0]), "+f"(d[1]), "+f"(d[2]), "+f"(d[3])
        : "r"(a.x), "r"(a.y), "r"(a.z), "r"(a.w), "r"(b0), "r"(b1));
}

} // namespace

__global__ __launch_bounds__(256, 1)
void conv1x3_shift_tf32(const float* __restrict__ x,
                        const float* __restrict__ wgt,
                        float* __restrict__ out) {
    extern __shared__ float smem[];
    float*    xs  = smem;                                        // x rows, padded
    unsigned* afr = reinterpret_cast<unsigned*>(smem + XS_FLOATS); // A fragments (tf32 bits)

    const int tid = threadIdx.x;
    const int blk = blockIdx.x;

    // --- zero padding columns: smem index 0 (w=-1) and 57 (w=56) -----------
    for (int p = tid; p < ROWS_PER_BLK * 128; p += 256) {
        xs[p * XSTRIDE + 0]  = 0.f;
        xs[p * XSTRIDE + 57] = 0.f;
    }

    // --- precompute A fragments (weights -> tf32, per-lane uint4 order) ----
    // e = r + 4*lane + 128*ks + 2048*m + 4096*kw
    for (int e = tid; e < AFR_U32; e += 256) {
        int r    = e & 3;
        int lane = (e >> 2) & 31;
        int ks   = (e >> 7) & 15;
        int m    = (e >> 11) & 1;
        int kw   = e >> 12;
        // m16n8k8 A frag: a0=(g,t) a1=(g+8,t) a2=(g,t+4) a3=(g+8,t+4)
        int o = m * 16 + (lane >> 2) + ((r & 1) << 3);
        int c = ks * 8 + (lane & 3) + ((r & 2) << 1);
        afr[e] = f2tf32(wgt[(o * 128 + c) * 3 + kw]);
    }

    // --- stage 4 x rows: x[n, c, hsrc, 0..55] -> xs[r][c][1..56] -----------
    for (int i = tid; i < ROWS_PER_BLK * 128 * 14; i += 256) {
        int r    = i / (128 * 14);
        int rem  = i - r * (128 * 14);
        int c    = rem / 14;
        int q    = rem - c * 14;
        int R    = blk * ROWS_PER_BLK + r;
        int n    = R / 56;
        int h    = R - n * 56;
        int hsrc = h ? (h - 1) : 55;   // roll(+1) on H
        const float4 v = *reinterpret_cast<const float4*>(
            x + ((n * 128 + c) * 56 + hsrc) * 56 + q * 4);
        float* dst = xs + (r * 128 + c) * XSTRIDE + 1 + q * 4;
        dst[0] = v.x; dst[1] = v.y; dst[2] = v.z; dst[3] = v.w;
    }

    __syncthreads();

    // --- compute: warp (r, half). half 0 -> w-tiles 0..3, half 1 -> 4..6 ---
    const int warp = tid >> 5;
    const int lane = tid & 31;
    const int r    = warp >> 1;
    const int half = warp & 1;
    const int g    = lane >> 2;   // group id (0..7)
    const int t    = lane & 3;    // thread-in-group (0..3)

    const float* xrow = xs + r * XS_PER_ROW;

    int wcol[4];
    #pragma unroll
    for (int j = 0; j < 4; j++) wcol[j] = g + 8 * (half * 4 + j);

    float acc[2][4][4];
    #pragma unroll
    for (int m = 0; m < 2; m++)
        #pragma unroll
        for (int j = 0; j < 4; j++)
            #pragma unroll
            for (int v = 0; v < 4; v++) acc[m][j][v] = 0.f;

    const uint4* afp = reinterpret_cast<const uint4*>(afr);

    #pragma unroll 4
    for (int ks = 0; ks < 16; ks++) {
        // B window: xs[c][wcol + kw], kw=0..2 -> 3 consecutive floats,
        // loaded once and shared across all three kw GEMMs.
        const float* bp = xrow + (ks * 8 + t) * XSTRIDE;
        float xv[2][4][3];
        #pragma unroll
        for (int kr = 0; kr < 2; kr++) {
            const float* p = bp + kr * 4 * XSTRIDE;   // k rows t and t+4
            #pragma unroll
            for (int j = 0; j < 4; j++) {
                if (half && j == 3) continue;          // tile 7 doesn't exist (N=56)
                const float* q = p + wcol[j];
                xv[kr][j][0] = q[0];
                xv[kr][j][1] = q[1];
                xv[kr][j][2] = q[2];
            }
        }
        #pragma unroll
        for (int kw = 0; kw < 3; kw++) {
            uint4 a0 = afp[((kw * 2 + 0) * 16 + ks) * 32 + lane];
            uint4 a1 = afp[((kw * 2 + 1) * 16 + ks) * 32 + lane];
            #pragma unroll
            for (int j = 0; j < 4; j++) {
                if (half && j == 3) continue;
                unsigned b0 = __float_as_uint(xv[0][j][kw]);
                unsigned b1 = __float_as_uint(xv[1][j][kw]);
                mma_tf32(acc[0][j], a0, b0, b1);
                mma_tf32(acc[1][j], a1, b0, b1);
            }
        }
    }

    // --- epilogue: C frag c0=(g,2t) c1=(g,2t+1) c2=(g+8,2t) c3=(g+8,2t+1) --
    {
        int R = blk * ROWS_PER_BLK + r;
        int n = R / 56;
        int h = R - n * 56;
        #pragma unroll
        for (int m = 0; m < 2; m++) {
            int o0 = m * 16 + g;
            #pragma unroll
            for (int j = 0; j < 4; j++) {
                if (half && j == 3) continue;
                int wc = 8 * (half * 4 + j) + 2 * t;   // even, < 56
                float* p0 = out + (n * 32 + o0) * 3136 + h * 56 + wc;
                *reinterpret_cast<float2*>(p0) =
                    make_float2(acc[m][j][0], acc[m][j][1]);
                float* p1 = p0 + 8 * 3136;              // o0 + 8
                *reinterpret_cast<float2*>(p1) =
                    make_float2(acc[m][j][2], acc[m][j][3]);
            }
        }
    }
}

extern "C" void kernel_launch(void* const* d_in, const int* in_sizes, int n_in,
                              void* d_out, int out_size) {
    const float* x   = (const float*)d_in[0];   // (128,128,56,56) f32
    const float* wgt = (const float*)d_in[1];   // (32,128,3) f32
    float*       out = (float*)d_out;           // (128,32,56,56) f32

    cudaFuncSetAttribute(conv1x3_shift_tf32,
                         cudaFuncAttributeMaxDynamicSharedMemorySize,
                         SMEM_BYTES);
    // 7168 (n,h) rows / 4 rows per block = 1792 blocks
    conv1x3_shift_tf32<<<1792, 256, SMEM_BYTES>>>(x, wgt, out);
}

// round 8
// speedup vs baseline: 1.7387x; 1.7387x over previous
#include <cuda_runtime.h>
#include <cstdint>

// ---------------------------------------------------------------------------
// out[n,o,h,w] = sum_{c,kw} x[n,c,(h-1)%56, w+kw-1] * wgt[o,c,kw]
// N=128, C=128, H=W=56, O=32, KW=3 (pad W by 1 each side).
// Per (n,h): GEMM C[32,56] = W[32,384] * X[384,56] via mma.sync.m16n8k8 tf32,
// as 3 accumulating K=128 GEMMs (one per kw) over shifted register windows.
// v2 (resubmit after infra failure): no x staging in smem — B fragments
// loaded directly from global with boundary predicates; only the 48KB
// A-fragment (weight) table lives in smem. smem 196KB->48KB, 1->3 CTAs/SM
// (24 warps), no stage/sync serialization.
// ---------------------------------------------------------------------------

namespace {

constexpr int ROWS_PER_BLK = 4;                   // (n,h) rows per block
constexpr int AFR_U32      = 3 * 2 * 16 * 32 * 4; // kw*mtile*ks*lane*4 = 12288
constexpr int CH_STRIDE    = 56 * 56;             // 3136 floats per (n,c) plane

__device__ __forceinline__ unsigned f2tf32(float f) {
    unsigned u;
    asm("cvt.rna.tf32.f32 %0, %1;" : "=r"(u) : "f"(f));
    return u;
}

__device__ __forceinline__ void mma_tf32(float d[4], const uint4& a,
                                         float b0f, float b1f) {
    unsigned b0 = __float_as_uint(b0f);
    unsigned b1 = __float_as_uint(b1f);
    asm volatile(
        "mma.sync.aligned.m16n8k8.row.col.f32.tf32.tf32.f32 "
        "{%0,%1,%2,%3}, {%4,%5,%6,%7}, {%8,%9}, {%0,%1,%2,%3};"
        : "+f"(d[0]), "+f"(d[1]), "+f"(d[2]), "+f"(d[3])
        : "r"(a.x), "r"(a.y), "r"(a.z), "r"(a.w), "r"(b0), "r"(b1));
}

} // namespace

__global__ __launch_bounds__(256, 3)
void conv1x3_shift_tf32_v2(const float* __restrict__ x,
                           const float* __restrict__ wgt,
                           float* __restrict__ out) {
    __shared__ unsigned afr[AFR_U32];   // 48 KB A-fragment table (tf32 bits)

    const int tid = threadIdx.x;
    const int blk = blockIdx.x;

    // --- build A fragments (weights -> tf32, per-lane uint4 order) ---------
    // e = reg + 4*lane + 128*ks + 2048*m + 4096*kw
    for (int e = tid; e < AFR_U32; e += 256) {
        int rr   = e & 3;
        int lane = (e >> 2) & 31;
        int ks   = (e >> 7) & 15;
        int m    = (e >> 11) & 1;
        int kw   = e >> 12;
        // m16n8k8 A frag: a0=(g,t) a1=(g+8,t) a2=(g,t+4) a3=(g+8,t+4)
        int o = m * 16 + (lane >> 2) + ((rr & 1) << 3);
        int c = ks * 8 + (lane & 3) + ((rr & 2) << 1);
        afr[e] = f2tf32(wgt[(o * 128 + c) * 3 + kw]);
    }
    __syncthreads();

    // --- per-warp setup: warp = (row r, half of the 7 w-tiles) -------------
    const int warp = tid >> 5;
    const int lane = tid & 31;
    const int r    = warp >> 1;
    const int half = warp & 1;
    const int g    = lane >> 2;   // group id (0..7)
    const int t    = lane & 3;    // thread-in-group (0..3)

    const int R    = blk * ROWS_PER_BLK + r;
    const int n    = R / 56;
    const int h    = R - n * 56;
    const int hsrc = h ? (h - 1) : 55;            // roll(+1) on H

    // base of x[n, :, hsrc, :]
    const float* xb = x + (size_t)n * (128 * CH_STRIDE) + (size_t)hsrc * 56;

    int  wcol[4];
    bool lo_ok[4], hi_ok[4];
    #pragma unroll
    for (int j = 0; j < 4; j++) {
        wcol[j]  = g + 8 * (half * 4 + j);
        lo_ok[j] = (wcol[j] > 0);                 // w-1 >= 0
        hi_ok[j] = (wcol[j] < 55);                // w+1 <  56
    }

    float acc[2][4][4];
    #pragma unroll
    for (int m = 0; m < 2; m++)
        #pragma unroll
        for (int j = 0; j < 4; j++)
            #pragma unroll
            for (int v = 0; v < 4; v++) acc[m][j][v] = 0.f;

    const uint4* afp = reinterpret_cast<const uint4*>(afr);

    // B k-rows for this lane: c = ks*8 + t (kr=0) and +4 (kr=1)
    const float* rp = xb + t * CH_STRIDE;

    #pragma unroll 2
    for (int ks = 0; ks < 16; ks++) {
        // load kw-window (3 consecutive floats) per (kr, j) straight from gmem
        float xv[2][4][3];
        #pragma unroll
        for (int kr = 0; kr < 2; kr++) {
            const float* pr = rp + kr * (4 * CH_STRIDE);
            #pragma unroll
            for (int j = 0; j < 4; j++) {
                if (half && j == 3) continue;     // tile 7 doesn't exist (W=56)
                const float* q = pr + (wcol[j] - 1);
                xv[kr][j][0] = lo_ok[j] ? q[0] : 0.f;
                xv[kr][j][1] = q[1];
                xv[kr][j][2] = hi_ok[j] ? q[2] : 0.f;
            }
        }
        #pragma unroll
        for (int kw = 0; kw < 3; kw++) {
            uint4 a0 = afp[((kw * 2 + 0) * 16 + ks) * 32 + lane];
            uint4 a1 = afp[((kw * 2 + 1) * 16 + ks) * 32 + lane];
            #pragma unroll
            for (int j = 0; j < 4; j++) {
                if (half && j == 3) continue;
                mma_tf32(acc[0][j], a0, xv[0][j][kw], xv[1][j][kw]);
                mma_tf32(acc[1][j], a1, xv[0][j][kw], xv[1][j][kw]);
            }
        }
        rp += 8 * CH_STRIDE;
    }

    // --- epilogue: C frag c0=(g,2t) c1=(g,2t+1) c2=(g+8,2t) c3=(g+8,2t+1) --
    #pragma unroll
    for (int m = 0; m < 2; m++) {
        int o0 = m * 16 + g;
        #pragma unroll
        for (int j = 0; j < 4; j++) {
            if (half && j == 3) continue;
            int wc = 8 * (half * 4 + j) + 2 * t;   // even, < 56
            float* p0 = out + ((size_t)n * 32 + o0) * CH_STRIDE + h * 56 + wc;
            *reinterpret_cast<float2*>(p0) =
                make_float2(acc[m][j][0], acc[m][j][1]);
            float* p1 = p0 + 8 * CH_STRIDE;        // o0 + 8
            *reinterpret_cast<float2*>(p1) =
                make_float2(acc[m][j][2], acc[m][j][3]);
        }
    }
}

extern "C" void kernel_launch(void* const* d_in, const int* in_sizes, int n_in,
                              void* d_out, int out_size) {
    const float* x   = (const float*)d_in[0];   // (128,128,56,56) f32
    const float* wgt = (const float*)d_in[1];   // (32,128,3) f32
    float*       out = (float*)d_out;           // (128,32,56,56) f32

    // 7168 (n,h) rows / 4 rows per block = 1792 blocks
    conv1x3_shift_tf32_v2<<<1792, 256>>>(x, wgt, out);
}